// round 9
// baseline (speedup 1.0000x reference)
#include <cuda_runtime.h>
#include <cstdint>

// Fixed shapes: points (4, 8192, 3) fp32
#define BATCH     4
#define NPTS      8192
#define NTOT      (BATCH * NPTS)
#define NN_SIZE   16
#define RADIUS2   0.25f
#define EPS_LOSS  1e-4f

// Spatial grid: cell width 0.25, domain [-5,5) clamped
#define GDIM      40
#define NCELLS    (GDIM * GDIM * GDIM)     // 64000
#define GMIN      (-5.0f)
#define INV_CW    4.0f
#define CW        0.25f

// Main kernel layout
#define SPLIT     8
#define TPB       256
#define QPB       (TPB / SPLIT)            // 32 queries per block
#define BPB       (NPTS / QPB)             // 256 blocks per batch
#define MROW      132                      // 8*16 + 4 pad

// Scan kernel layout
#define SCAN_T    256
#define SCAN_CPT  (NCELLS / SCAN_T)        // 250

// g_count: zero at module load; k_scan restores it to zero every run.
__device__ int    g_count [BATCH * NCELLS];
__device__ int    g_start [BATCH * NCELLS];   // excl prefix; becomes END after scatter
__device__ float4 g_sorted[NTOT];
__device__ int    g_sid   [NTOT];             // sorted pos -> original index
__device__ float  g_loss  [NTOT];             // per ORIGINAL index (deterministic)

__device__ __forceinline__ int cell_of(float x, float y, float z) {
    int cx = (int)floorf((x - GMIN) * INV_CW);
    int cy = (int)floorf((y - GMIN) * INV_CW);
    int cz = (int)floorf((z - GMIN) * INV_CW);
    cx = min(max(cx, 0), GDIM - 1);
    cy = min(max(cy, 0), GDIM - 1);
    cz = min(max(cz, 0), GDIM - 1);
    return (cz * GDIM + cy) * GDIM + cx;
}

__global__ void k_count(const float* __restrict__ pts) {
    int i = blockIdx.x * blockDim.x + threadIdx.x;
    if (i >= NTOT) return;
    int b = i >> 13;
    float x = pts[3 * i + 0], y = pts[3 * i + 1], z = pts[3 * i + 2];
    atomicAdd(&g_count[b * NCELLS + cell_of(x, y, z)], 1);
}

// Exclusive scan per batch (one block per batch); zeroes g_count after reading.
__global__ __launch_bounds__(SCAN_T) void k_scan() {
    __shared__ int wsum[SCAN_T / 32];
    const int b = blockIdx.x;
    const int t = threadIdx.x;
    const int lane = t & 31, warp = t >> 5;
    const int base = b * NCELLS + t * SCAN_CPT;

    int tot = 0;
    for (int i = 0; i < SCAN_CPT; ++i) tot += g_count[base + i];

    int inc = tot;
#pragma unroll
    for (int off = 1; off < 32; off <<= 1) {
        int n = __shfl_up_sync(0xffffffffu, inc, off);
        if (lane >= off) inc += n;
    }
    if (lane == 31) wsum[warp] = inc;
    __syncthreads();
    if (warp == 0 && lane < SCAN_T / 32) {
        int w = wsum[lane];
#pragma unroll
        for (int off = 1; off < SCAN_T / 32; off <<= 1) {
            int n = __shfl_up_sync(0xffu, w, off);
            if (lane >= off) w += n;
        }
        wsum[lane] = w;
    }
    __syncthreads();
    int run = inc - tot + (warp ? wsum[warp - 1] : 0);
    for (int i = 0; i < SCAN_CPT; ++i) {
        int v = g_count[base + i];
        g_start[base + i] = run;
        run += v;
        g_count[base + i] = 0;          // self-restore for next graph replay
    }
}

// Scatter; atomic consume of g_start turns it into the END-offset array.
__global__ void k_scatter(const float* __restrict__ pts) {
    int i = blockIdx.x * blockDim.x + threadIdx.x;
    if (i >= NTOT) return;
    int b = i >> 13;
    float x = pts[3 * i + 0], y = pts[3 * i + 1], z = pts[3 * i + 2];
    int c = cell_of(x, y, z);
    int pos = atomicAdd(&g_start[b * NCELLS + c], 1);
    float w = 0.5f * (x * x + y * y + z * z);
    g_sorted[b * NPTS + pos] = make_float4(x, y, z, w);
    g_sid[b * NPTS + pos] = i - b * NPTS;
}

// Branchless sorted insert (ascending), drop a[15].
__device__ __forceinline__ void sorted_insert16(float (&a)[16], float v) {
#pragma unroll
    for (int k = 15; k > 0; --k) {
        a[k] = fminf(fmaxf(v, a[k - 1]), a[k]);
    }
    a[0] = fminf(a[0], v);
}

// Scan one contiguous run [k0,k1); this lane takes k0+s, +SPLIT, ...
__device__ __forceinline__ void scan_run(const float4* __restrict__ spts,
                                         int k0, int k1, int s, int g,
                                         float nqx, float nqy, float nqz,
                                         float (&a)[16]) {
    for (int k = k0 + s; k < k1; k += SPLIT) {
        float4 cd = spts[k];
        float e = fmaf(cd.x, nqx, fmaf(cd.y, nqy, fmaf(cd.z, nqz, cd.w)));
        if (e < a[15] && k != g) sorted_insert16(a, e);
    }
}

__global__ __launch_bounds__(TPB) void k_main() {
    __shared__ float mbuf[QPB * MROW];     // 16.9 KB
    __shared__ float qw_s[QPB];

    const int t  = threadIdx.x;
    const int ql = t >> 3;                  // local query 0..31
    const int s  = t & 7;                   // split lane 0..7
    const int b  = blockIdx.x / BPB;
    const int g  = (blockIdx.x % BPB) * QPB + ql;   // sorted query position

    const float4* __restrict__ spts = &g_sorted[b * NPTS];
    const int*    __restrict__ cend = &g_start[b * NCELLS];   // end offsets

    const float4 qp = spts[g];
    const float nqx = -qp.x, nqy = -qp.y, nqz = -qp.z;
    const float ecap = 0.5f * RADIUS2 - qp.w;       // e < ecap  <=>  d^2 < R^2
    if (s == 0) qw_s[ql] = qp.w;

    float a[16];
#pragma unroll
    for (int k = 0; k < 16; ++k) a[k] = ecap;

    int cx = (int)floorf((qp.x - GMIN) * INV_CW);
    int cy = (int)floorf((qp.y - GMIN) * INV_CW);
    int cz = (int)floorf((qp.z - GMIN) * INV_CW);
    cx = min(max(cx, 0), GDIM - 1);
    cy = min(max(cy, 0), GDIM - 1);
    cz = min(max(cz, 0), GDIM - 1);

    const int ORD[5] = {0, -1, 1, -2, 2};   // closest rows first

    for (int iz = 0; iz < 5; ++iz) {
        int nz = cz + ORD[iz];
        if ((unsigned)nz >= GDIM) continue;
        float zlo = GMIN + (float)nz * CW;
        float zd  = fmaxf(0.0f, fmaxf(zlo - qp.z, qp.z - (zlo + CW)));
        float zd2 = zd * zd;
        if (zd2 >= RADIUS2 + 1e-5f) continue;
        for (int iy = 0; iy < 5; ++iy) {
            int ny = cy + ORD[iy];
            if ((unsigned)ny >= GDIM) continue;
            float ylo = GMIN + (float)ny * CW;
            float yd  = fmaxf(0.0f, fmaxf(ylo - qp.y, qp.y - (ylo + CW)));
            float yz2 = fmaf(yd, yd, zd2);
            if (yz2 >= RADIUS2 + 1e-5f) continue;   // exact row prune (+margin)

            // Exact x-extent (over-inclusive margin -> safe)
            float xr = sqrtf(fmaxf(RADIUS2 - yz2, 0.0f)) + 1e-3f;
            int xa = max((int)floorf((qp.x - xr - GMIN) * INV_CW), 0);
            int xb = min((int)floorf((qp.x + xr - GMIN) * INV_CW), GDIM - 1);
            if (xa > xb) continue;

            int row = (nz * GDIM + ny) * GDIM;
            int c0 = row + xa;
            int k0 = (c0 == 0) ? 0 : cend[c0 - 1];
            int k1 = cend[row + xb];
            scan_run(spts, k0, k1, s, g, nqx, nqy, nqz, a);
        }
    }

    // Dump 8 sorted 16-lists per query.
#pragma unroll
    for (int k = 0; k < 16; ++k) {
        mbuf[ql * MROW + (s << 4) + k] = a[k];
    }
    __syncthreads();

    // One thread per query: 16-step 8-way pointer merge in ascending-e order.
    if (t < QPB) {
        const float* L   = &mbuf[t * MROW];
        const float  w   = qw_s[t];
        const float  cap = 0.5f * RADIUS2 - w;
        float part = 0.0f;
        int p[8];
#pragma unroll
        for (int i = 0; i < 8; ++i) p[i] = i << 4;
#pragma unroll 1
        for (int it = 0; it < NN_SIZE; ++it) {
            float h0 = L[p[0]], h1 = L[p[1]], h2 = L[p[2]], h3 = L[p[3]];
            float h4 = L[p[4]], h5 = L[p[5]], h6 = L[p[6]], h7 = L[p[7]];
            float m = fminf(fminf(fminf(h0, h1), fminf(h2, h3)),
                            fminf(fminf(h4, h5), fminf(h6, h7)));
            if (m >= cap) break;           // rest are sentinels / out of radius
            part += rsqrtf(fmaf(2.0f, w + m, EPS_LOSS));   // d^2 = 2*(w+e)
            if      (m == h0) ++p[0];
            else if (m == h1) ++p[1];
            else if (m == h2) ++p[2];
            else if (m == h3) ++p[3];
            else if (m == h4) ++p[4];
            else if (m == h5) ++p[5];
            else if (m == h6) ++p[6];
            else              ++p[7];
        }
        int gq  = (blockIdx.x % BPB) * QPB + t;
        int oid = g_sid[b * NPTS + gq];
        g_loss[b * NPTS + oid] = part;
    }
}

// Deterministic fixed-order reduction of 32768 per-query losses.
__global__ __launch_bounds__(1024) void k_final(float* __restrict__ out) {
    __shared__ float r[1024];
    const int t = threadIdx.x;
    float s = 0.0f;
#pragma unroll
    for (int i = 0; i < NTOT / 1024; ++i) {
        s += g_loss[i * 1024 + t];
    }
    r[t] = s;
    __syncthreads();
#pragma unroll
    for (int off = 512; off > 0; off >>= 1) {
        if (t < off) r[t] += r[t + off];
        __syncthreads();
    }
    if (t == 0) out[0] = r[0] * (1.0f / (float)(NTOT * NN_SIZE));
}

extern "C" void kernel_launch(void* const* d_in, const int* in_sizes, int n_in,
                              void* d_out, int out_size) {
    (void)in_sizes; (void)n_in; (void)out_size;
    const float* pts = (const float*)d_in[0];
    float* out = (float*)d_out;

    k_count  <<<(NTOT + 255) / 256, 256>>>(pts);   // idx 0
    k_scan   <<<BATCH, SCAN_T>>>();                // idx 1
    k_scatter<<<(NTOT + 255) / 256, 256>>>(pts);   // idx 2
    k_main   <<<BATCH * BPB, TPB>>>();             // idx 3  <- ncu -s 5 lands here
    k_final  <<<1, 1024>>>(out);                   // idx 4
}

// round 10
// speedup vs baseline: 3.3101x; 3.3101x over previous
#include <cuda_runtime.h>
#include <cstdint>

// Fixed shapes: points (4, 8192, 3) fp32
#define BATCH     4
#define NPTS      8192
#define NTOT      (BATCH * NPTS)
#define NN_SIZE   16
#define RADIUS2   0.25f
#define EPS_LOSS  1e-4f

// Spatial grid: cell width 0.5 (= radius), domain [-5,5) clamped
#define GDIM      20
#define NCELLS    (GDIM * GDIM * GDIM)     // 8000
#define GMIN      (-5.0f)
#define INV_CW    2.0f
#define CW        0.5f

// Main kernel layout
#define SPLIT     4
#define TPB       128
#define QPB       (TPB / SPLIT)            // 32 queries per block
#define BPB       (NPTS / QPB)             // 256 blocks per batch
#define MROW      65                       // conflict-free merge-row stride

// Scan kernel layout
#define SCAN_T    256
#define CPT       32                       // 256*32 = 8192 >= 8000

// g_count zero at module load; k_scan restores it to zero every run.
__device__ int    g_count [BATCH * NCELLS];
__device__ int    g_start [BATCH * NCELLS];   // excl prefix; becomes END after scatter
__device__ float4 g_sorted[NTOT];
__device__ int    g_sid   [NTOT];             // sorted pos -> original index
__device__ float  g_loss  [NTOT];             // per ORIGINAL index

__device__ __forceinline__ int cell_of(float x, float y, float z) {
    int cx = (int)floorf((x - GMIN) * INV_CW);
    int cy = (int)floorf((y - GMIN) * INV_CW);
    int cz = (int)floorf((z - GMIN) * INV_CW);
    cx = min(max(cx, 0), GDIM - 1);
    cy = min(max(cy, 0), GDIM - 1);
    cz = min(max(cz, 0), GDIM - 1);
    return (cz * GDIM + cy) * GDIM + cx;
}

__global__ void k_count(const float* __restrict__ pts) {
    int i = blockIdx.x * blockDim.x + threadIdx.x;
    if (i >= NTOT) return;
    int b = i >> 13;
    float x = pts[3 * i + 0], y = pts[3 * i + 1], z = pts[3 * i + 2];
    atomicAdd(&g_count[b * NCELLS + cell_of(x, y, z)], 1);
}

// Register-blocked exclusive scan per batch; self-zeroes g_count after reading.
__global__ __launch_bounds__(SCAN_T) void k_scan() {
    __shared__ int wsum[SCAN_T / 32];
    const int b = blockIdx.x;
    const int t = threadIdx.x;
    const int lane = t & 31, warp = t >> 5;
    const int base = t * CPT;

    int v[CPT];
    int tot = 0;
#pragma unroll
    for (int i = 0; i < CPT; ++i) {
        int c = base + i;
        v[i] = (c < NCELLS) ? g_count[b * NCELLS + c] : 0;
        tot += v[i];
    }
    int inc = tot;
#pragma unroll
    for (int off = 1; off < 32; off <<= 1) {
        int n = __shfl_up_sync(0xffffffffu, inc, off);
        if (lane >= off) inc += n;
    }
    if (lane == 31) wsum[warp] = inc;
    __syncthreads();
    if (warp == 0 && lane < SCAN_T / 32) {
        int w = wsum[lane];
#pragma unroll
        for (int off = 1; off < SCAN_T / 32; off <<= 1) {
            int n = __shfl_up_sync(0xffu, w, off);
            if (lane >= off) w += n;
        }
        wsum[lane] = w;
    }
    __syncthreads();
    int excl = inc - tot + (warp ? wsum[warp - 1] : 0);
#pragma unroll
    for (int i = 0; i < CPT; ++i) {
        int c = base + i;
        if (c < NCELLS) {
            g_start[b * NCELLS + c] = excl;
            g_count[b * NCELLS + c] = 0;   // self-restore for next run
        }
        excl += v[i];
    }
}

// Scatter; atomic consume of g_start turns it into the END-offset array.
__global__ void k_scatter(const float* __restrict__ pts) {
    int i = blockIdx.x * blockDim.x + threadIdx.x;
    if (i >= NTOT) return;
    int b = i >> 13;
    float x = pts[3 * i + 0], y = pts[3 * i + 1], z = pts[3 * i + 2];
    int c = cell_of(x, y, z);
    int pos = atomicAdd(&g_start[b * NCELLS + c], 1);
    float w = 0.5f * (x * x + y * y + z * z);
    g_sorted[b * NPTS + pos] = make_float4(x, y, z, w);
    g_sid[b * NPTS + pos] = i - b * NPTS;
}

// Branchless sorted insert (ascending), drop a[15].
__device__ __forceinline__ void sorted_insert16(float (&a)[16], float v) {
#pragma unroll
    for (int k = 15; k > 0; --k) {
        a[k] = fminf(fmaxf(v, a[k - 1]), a[k]);
    }
    a[0] = fminf(a[0], v);
}

__global__ __launch_bounds__(TPB) void k_main() {
    __shared__ float mbuf [QPB * MROW];    // 8.3 KB (heavy-path merge lists)
    __shared__ float qw_s [QPB];
    __shared__ float sum_s[QPB];
    __shared__ int   cnt_s[QPB];

    const int t    = threadIdx.x;
    const int ql   = t >> 2;                // local query 0..31
    const int s    = t & 3;                 // split lane 0..3
    const int lane = t & 31;
    const int b    = blockIdx.x / BPB;
    const int g    = (blockIdx.x % BPB) * QPB + ql;   // sorted query position

    const float4* __restrict__ spts = &g_sorted[b * NPTS];
    const int*    __restrict__ cend = &g_start[b * NCELLS];

    const float4 qp = spts[g];
    const float nqx = -qp.x, nqy = -qp.y, nqz = -qp.z;
    const float ecap = 0.5f * RADIUS2 - qp.w;       // e < ecap  <=>  d^2 < R^2
    if (s == 0) qw_s[ql] = qp.w;

    int cx = (int)floorf((qp.x - GMIN) * INV_CW);
    int cy = (int)floorf((qp.y - GMIN) * INV_CW);
    int cz = (int)floorf((qp.z - GMIN) * INV_CW);
    cx = min(max(cx, 0), GDIM - 1);
    cy = min(max(cy, 0), GDIM - 1);
    cz = min(max(cz, 0), GDIM - 1);

    // Collect candidate row-ranges (<=9 rows), with exact slab prune + x-trim.
    int r0[9], r1[9];
    int nr = 0;
#pragma unroll
    for (int dz = -1; dz <= 1; ++dz) {
        int nz = cz + dz;
        if ((unsigned)nz >= GDIM) continue;
        float zlo = GMIN + (float)nz * CW;
        float zd  = fmaxf(0.0f, fmaxf(zlo - qp.z, qp.z - (zlo + CW)));
        float zd2 = zd * zd;
#pragma unroll
        for (int dy = -1; dy <= 1; ++dy) {
            int ny = cy + dy;
            if ((unsigned)ny >= GDIM) continue;
            float ylo = GMIN + (float)ny * CW;
            float yd  = fmaxf(0.0f, fmaxf(ylo - qp.y, qp.y - (ylo + CW)));
            float yz2 = fmaf(yd, yd, zd2);
            if (yz2 >= RADIUS2 + 1e-5f) continue;      // exact row prune
            float xr = sqrtf(RADIUS2 - yz2) + 1e-3f;   // over-inclusive (safe)
            int xa = max((int)floorf((qp.x - xr - GMIN) * INV_CW), 0);
            int xb = min((int)floorf((qp.x + xr - GMIN) * INV_CW), GDIM - 1);
            if (xa > xb) continue;
            int row = (nz * GDIM + ny) * GDIM;
            int c0  = row + xa;
            r0[nr] = (c0 == 0) ? 0 : cend[c0 - 1];
            r1[nr] = cend[row + xb];
            ++nr;
        }
    }

    // ---- Pass A: count + sum of in-radius hits (constant threshold: no
    //      dependent chain, no insert network). ----
    int   cnt  = 0;
    float ssum = 0.0f;
    for (int r = 0; r < nr; ++r) {
        for (int k = r0[r] + s; k < r1[r]; k += SPLIT) {
            float4 cd = spts[k];
            float e = fmaf(cd.x, nqx, fmaf(cd.y, nqy, fmaf(cd.z, nqz, cd.w)));
            if (e < ecap && k != g) {
                ++cnt;
                ssum += rsqrtf(fmaf(2.0f, qp.w + e, EPS_LOSS));  // d^2 = 2(w+e)
            }
        }
    }

    // Ordered 4-lane group reduce (fixed order -> deterministic given binning).
    const unsigned FULL = 0xffffffffu;
    const int gb = lane & ~3;
    float s0 = __shfl_sync(FULL, ssum, gb + 0);
    float s1 = __shfl_sync(FULL, ssum, gb + 1);
    float s2 = __shfl_sync(FULL, ssum, gb + 2);
    float s3 = __shfl_sync(FULL, ssum, gb + 3);
    int   c0 = __shfl_sync(FULL, cnt,  gb + 0);
    int   c1 = __shfl_sync(FULL, cnt,  gb + 1);
    int   c2 = __shfl_sync(FULL, cnt,  gb + 2);
    int   c3 = __shfl_sync(FULL, cnt,  gb + 3);
    float stot = (s0 + s1) + (s2 + s3);
    int   ctot = (c0 + c1) + (c2 + c3);

    if (s == 0) {
        cnt_s[ql] = ctot;
        sum_s[ql] = stot;
    }

    // ---- Heavy path (ctot > 16): rescan saved ranges with top-16 selection. ----
    if (ctot > NN_SIZE) {
        float a[16];
#pragma unroll
        for (int k = 0; k < 16; ++k) a[k] = ecap;
        for (int r = 0; r < nr; ++r) {
            for (int k = r0[r] + s; k < r1[r]; k += SPLIT) {
                float4 cd = spts[k];
                float e = fmaf(cd.x, nqx, fmaf(cd.y, nqy, fmaf(cd.z, nqz, cd.w)));
                if (e < a[15] && k != g) sorted_insert16(a, e);
            }
        }
#pragma unroll
        for (int k = 0; k < 16; ++k) {
            mbuf[ql * MROW + (s << 4) + k] = a[k];
        }
    }
    __syncthreads();

    // One thread per query: light -> precomputed sum; heavy -> 4-way merge.
    if (t < QPB) {
        float part;
        if (cnt_s[t] <= NN_SIZE) {
            part = sum_s[t];
        } else {
            const float* L   = &mbuf[t * MROW];
            const float  w   = qw_s[t];
            const float  cap = 0.5f * RADIUS2 - w;
            part = 0.0f;
            int p0 = 0, p1 = 16, p2 = 32, p3 = 48;
#pragma unroll 1
            for (int it = 0; it < NN_SIZE; ++it) {
                float h0 = L[p0], h1 = L[p1], h2 = L[p2], h3 = L[p3];
                float m = fminf(fminf(h0, h1), fminf(h2, h3));
                if (m >= cap) break;
                part += rsqrtf(fmaf(2.0f, w + m, EPS_LOSS));
                if      (m == h0) ++p0;
                else if (m == h1) ++p1;
                else if (m == h2) ++p2;
                else              ++p3;
            }
        }
        int gq  = (blockIdx.x % BPB) * QPB + t;
        int oid = g_sid[b * NPTS + gq];
        g_loss[b * NPTS + oid] = part;
    }
}

// Deterministic fixed-order reduction of 32768 per-query losses.
__global__ __launch_bounds__(1024) void k_final(float* __restrict__ out) {
    __shared__ float r[1024];
    const int t = threadIdx.x;
    float s = 0.0f;
#pragma unroll
    for (int i = 0; i < NTOT / 1024; ++i) {
        s += g_loss[i * 1024 + t];
    }
    r[t] = s;
    __syncthreads();
#pragma unroll
    for (int off = 512; off > 0; off >>= 1) {
        if (t < off) r[t] += r[t + off];
        __syncthreads();
    }
    if (t == 0) out[0] = r[0] * (1.0f / (float)(NTOT * NN_SIZE));
}

extern "C" void kernel_launch(void* const* d_in, const int* in_sizes, int n_in,
                              void* d_out, int out_size) {
    (void)in_sizes; (void)n_in; (void)out_size;
    const float* pts = (const float*)d_in[0];
    float* out = (float*)d_out;

    k_count  <<<(NTOT + 255) / 256, 256>>>(pts);   // idx 0
    k_scan   <<<BATCH, SCAN_T>>>();                // idx 1
    k_scatter<<<(NTOT + 255) / 256, 256>>>(pts);   // idx 2
    k_main   <<<BATCH * BPB, TPB>>>();             // idx 3  <- ncu -s 5 lands here
    k_final  <<<1, 1024>>>(out);                   // idx 4
}

// round 11
// speedup vs baseline: 5.8847x; 1.7778x over previous
#include <cuda_runtime.h>
#include <cstdint>

// Fixed shapes: points (4, 8192, 3) fp32
#define BATCH     4
#define NPTS      8192
#define NTOT      (BATCH * NPTS)
#define NN_SIZE   16
#define RADIUS2   0.25f
#define EPS_LOSS  1e-4f

// Spatial grid: cell width 0.25, domain [-5,5) clamped
#define GDIM      40
#define NCELLS    (GDIM * GDIM * GDIM)     // 64000 per batch
#define GMIN      (-5.0f)
#define INV_CW    4.0f
#define CW        0.25f

// Hierarchical scan: 64 segments x 1000 cells per batch
#define NSEG      64
#define SEGC      (NCELLS / NSEG)          // 1000
#define SCANC_T   256

// Main kernel layout
#define SPLIT     4
#define TPB       128
#define QPB       (TPB / SPLIT)            // 32 queries per block
#define BPB       (NPTS / QPB)             // 256 blocks per batch
#define NBLK      (BATCH * BPB)            // 1024
#define MROW      65                       // conflict-free merge-row stride

// All zero at module load; each is self-restored every run for graph replay.
__device__ int      g_count [BATCH * NCELLS];
__device__ int      g_start [BATCH * NCELLS];  // excl prefix; becomes END after scatter
__device__ int      g_part  [BATCH * NSEG];    // segment totals -> excl offsets
__device__ float4   g_sorted[NTOT + 16];       // +pad for unconditional prefetch
__device__ int      g_sid   [NTOT];            // sorted pos -> original index
__device__ float    g_loss  [NTOT];            // per ORIGINAL index (deterministic)
__device__ unsigned g_done;                    // k_main completion ticket

__device__ __forceinline__ int cell_of(float x, float y, float z) {
    int cx = (int)floorf((x - GMIN) * INV_CW);
    int cy = (int)floorf((y - GMIN) * INV_CW);
    int cz = (int)floorf((z - GMIN) * INV_CW);
    cx = min(max(cx, 0), GDIM - 1);
    cy = min(max(cy, 0), GDIM - 1);
    cz = min(max(cz, 0), GDIM - 1);
    return (cz * GDIM + cy) * GDIM + cx;
}

__global__ void k_count(const float* __restrict__ pts) {
    int i = blockIdx.x * blockDim.x + threadIdx.x;
    if (i >= NTOT) return;
    int b = i >> 13;
    float x = pts[3 * i + 0], y = pts[3 * i + 1], z = pts[3 * i + 2];
    atomicAdd(&g_count[b * NCELLS + cell_of(x, y, z)], 1);
}

// Segment totals: one block per (batch, segment).
__global__ __launch_bounds__(SCANC_T) void k_scanA() {
    __shared__ int red[SCANC_T];
    const int blk = blockIdx.x;               // 0..BATCH*NSEG-1
    const int b   = blk / NSEG;
    const int seg = blk % NSEG;
    const int t   = threadIdx.x;
    const int base = b * NCELLS + seg * SEGC;
    int s = 0;
    for (int i = t; i < SEGC; i += SCANC_T) s += g_count[base + i];
    red[t] = s;
    __syncthreads();
#pragma unroll
    for (int off = SCANC_T / 2; off > 0; off >>= 1) {
        if (t < off) red[t] += red[t + off];
        __syncthreads();
    }
    if (t == 0) g_part[blk] = red[0];
}

// Per-batch exclusive scan of the 64 segment totals (tiny; 4 serial threads).
__global__ void k_scanB() {
    int t = threadIdx.x;
    if (t < BATCH) {
        int base = t * NSEG;
        int run = 0;
        for (int i = 0; i < NSEG; ++i) {
            int v = g_part[base + i];
            g_part[base + i] = run;
            run += v;
        }
    }
}

// Local exclusive scan per segment + global offset; self-zeroes g_count.
__global__ __launch_bounds__(SCANC_T) void k_scanC() {
    __shared__ int wsum[SCANC_T / 32];
    const int blk = blockIdx.x;
    const int b   = blk / NSEG;
    const int seg = blk % NSEG;
    const int t   = threadIdx.x;
    const int lane = t & 31, warp = t >> 5;
    const int base = b * NCELLS + seg * SEGC;
    const int goff = g_part[blk];

    // 4 cells per thread (256*4 = 1024 >= 1000)
    int v[4];
    int tot = 0;
#pragma unroll
    for (int j = 0; j < 4; ++j) {
        int c = t * 4 + j;
        v[j] = (c < SEGC) ? g_count[base + c] : 0;
        tot += v[j];
    }
    int inc = tot;
#pragma unroll
    for (int off = 1; off < 32; off <<= 1) {
        int n = __shfl_up_sync(0xffffffffu, inc, off);
        if (lane >= off) inc += n;
    }
    if (lane == 31) wsum[warp] = inc;
    __syncthreads();
    if (warp == 0 && lane < SCANC_T / 32) {
        int w = wsum[lane];
#pragma unroll
        for (int off = 1; off < SCANC_T / 32; off <<= 1) {
            int n = __shfl_up_sync(0xffu, w, off);
            if (lane >= off) w += n;
        }
        wsum[lane] = w;
    }
    __syncthreads();
    int excl = goff + inc - tot + (warp ? wsum[warp - 1] : 0);
#pragma unroll
    for (int j = 0; j < 4; ++j) {
        int c = t * 4 + j;
        if (c < SEGC) {
            g_start[base + c] = excl;
            g_count[base + c] = 0;          // self-restore for next replay
        }
        excl += v[j];
    }
}

// Scatter; atomic consume of g_start turns it into the END-offset array.
__global__ void k_scatter(const float* __restrict__ pts) {
    int i = blockIdx.x * blockDim.x + threadIdx.x;
    if (i >= NTOT) return;
    int b = i >> 13;
    float x = pts[3 * i + 0], y = pts[3 * i + 1], z = pts[3 * i + 2];
    int c = cell_of(x, y, z);
    int pos = atomicAdd(&g_start[b * NCELLS + c], 1);
    float w = 0.5f * (x * x + y * y + z * z);
    g_sorted[b * NPTS + pos] = make_float4(x, y, z, w);
    g_sid[b * NPTS + pos] = i - b * NPTS;
}

// Branchless sorted insert (ascending), drop a[15].
__device__ __forceinline__ void sorted_insert16(float (&a)[16], float v) {
#pragma unroll
    for (int k = 15; k > 0; --k) {
        a[k] = fminf(fmaxf(v, a[k - 1]), a[k]);
    }
    a[0] = fminf(a[0], v);
}

// 2x-unrolled run scan with unconditional prefetch (g_sorted padded).
__device__ __forceinline__ void scan_run(const float4* __restrict__ spts,
                                         int k0, int k1, int s, int g,
                                         float nqx, float nqy, float nqz,
                                         float (&a)[16]) {
    int k = k0 + s;
    for (; k + SPLIT < k1; k += 2 * SPLIT) {
        float4 c0 = spts[k];
        float4 c1 = spts[k + SPLIT];          // always in-bounds of padded array
        float e0 = fmaf(c0.x, nqx, fmaf(c0.y, nqy, fmaf(c0.z, nqz, c0.w)));
        float e1 = fmaf(c1.x, nqx, fmaf(c1.y, nqy, fmaf(c1.z, nqz, c1.w)));
        if (e0 < a[15] && k != g) sorted_insert16(a, e0);
        if (e1 < a[15] && (k + SPLIT) != g) sorted_insert16(a, e1);
    }
    if (k < k1) {
        float4 c0 = spts[k];
        float e0 = fmaf(c0.x, nqx, fmaf(c0.y, nqy, fmaf(c0.z, nqz, c0.w)));
        if (e0 < a[15] && k != g) sorted_insert16(a, e0);
    }
}

__global__ __launch_bounds__(TPB) void k_main(float* __restrict__ out) {
    __shared__ float mbuf[QPB * MROW];     // 8.3 KB
    __shared__ float qw_s[QPB];
    __shared__ int   last_s;

    const int t  = threadIdx.x;
    const int ql = t >> 2;                  // local query 0..31
    const int s  = t & 3;                   // split lane 0..3
    const int b  = blockIdx.x / BPB;
    // Heavy-first permutation: dense cloud-center queries live in middle
    // block indices of the sorted order; launch them first to shrink the tail.
    const int i  = blockIdx.x % BPB;
    const int blkq = (i & 1) ? (BPB / 2 + (i >> 1)) : (BPB / 2 - 1 - (i >> 1));
    const int g  = blkq * QPB + ql;         // sorted query position

    const float4* __restrict__ spts = &g_sorted[b * NPTS];
    const int*    __restrict__ cend = &g_start[b * NCELLS];

    const float4 qp = spts[g];
    const float nqx = -qp.x, nqy = -qp.y, nqz = -qp.z;
    const float ecap = 0.5f * RADIUS2 - qp.w;       // e < ecap  <=>  d^2 < R^2
    if (s == 0) qw_s[ql] = qp.w;

    float a[16];
#pragma unroll
    for (int k = 0; k < 16; ++k) a[k] = ecap;

    int cx = (int)floorf((qp.x - GMIN) * INV_CW);
    int cy = (int)floorf((qp.y - GMIN) * INV_CW);
    int cz = (int)floorf((qp.z - GMIN) * INV_CW);
    cx = min(max(cx, 0), GDIM - 1);
    cy = min(max(cy, 0), GDIM - 1);
    cz = min(max(cz, 0), GDIM - 1);

    const int ORD[5] = {0, -1, 1, -2, 2};   // closest rows first

    for (int iz = 0; iz < 5; ++iz) {
        int nz = cz + ORD[iz];
        if ((unsigned)nz >= GDIM) continue;
        float zlo = GMIN + (float)nz * CW;
        float zd  = fmaxf(0.0f, fmaxf(zlo - qp.z, qp.z - (zlo + CW)));
        float zd2 = zd * zd;
        if (zd2 >= RADIUS2 + 1e-5f) continue;
        for (int iy = 0; iy < 5; ++iy) {
            int ny = cy + ORD[iy];
            if ((unsigned)ny >= GDIM) continue;
            float ylo = GMIN + (float)ny * CW;
            float yd  = fmaxf(0.0f, fmaxf(ylo - qp.y, qp.y - (ylo + CW)));
            float yz2 = fmaf(yd, yd, zd2);
            if (yz2 >= RADIUS2 + 1e-5f) continue;   // exact row prune (+margin)

            float xr = sqrtf(fmaxf(RADIUS2 - yz2, 0.0f)) + 1e-3f;  // over-incl. safe
            int xa = max((int)floorf((qp.x - xr - GMIN) * INV_CW), 0);
            int xb = min((int)floorf((qp.x + xr - GMIN) * INV_CW), GDIM - 1);
            if (xa > xb) continue;

            int row = (nz * GDIM + ny) * GDIM;
            int c0  = row + xa;
            int k0  = (c0 == 0) ? 0 : cend[c0 - 1];
            int k1  = cend[row + xb];
            scan_run(spts, k0, k1, s, g, nqx, nqy, nqz, a);
        }
    }

    // Dump 4 sorted 16-lists per query.
#pragma unroll
    for (int k = 0; k < 16; ++k) {
        mbuf[ql * MROW + (s << 4) + k] = a[k];
    }
    __syncthreads();

    // One thread per query: 16-step 4-way pointer merge, ascending-e order.
    if (t < QPB) {
        const float* L   = &mbuf[t * MROW];
        const float  w   = qw_s[t];
        const float  cap = 0.5f * RADIUS2 - w;
        float part = 0.0f;
        int p0 = 0, p1 = 16, p2 = 32, p3 = 48;
#pragma unroll 1
        for (int it = 0; it < NN_SIZE; ++it) {
            float h0 = L[p0], h1 = L[p1], h2 = L[p2], h3 = L[p3];
            float m = fminf(fminf(h0, h1), fminf(h2, h3));
            if (m >= cap) break;
            part += rsqrtf(fmaf(2.0f, w + m, EPS_LOSS));   // d^2 = 2*(w+e)
            if      (m == h0) ++p0;
            else if (m == h1) ++p1;
            else if (m == h2) ++p2;
            else              ++p3;
        }
        int oid = g_sid[b * NPTS + blkq * QPB + t];
        g_loss[b * NPTS + oid] = part;
    }

    // Last-block fixed-order final reduction (deterministic; saves a launch).
    __threadfence();
    __syncthreads();
    if (t == 0) {
        unsigned ticket = atomicAdd(&g_done, 1u);
        last_s = (ticket == NBLK - 1) ? 1 : 0;
    }
    __syncthreads();
    if (last_s) {
        __shared__ float r[TPB];
        float sum = 0.0f;
#pragma unroll
        for (int j = 0; j < NTOT / TPB; ++j) {
            sum += g_loss[j * TPB + t];
        }
        r[t] = sum;
        __syncthreads();
#pragma unroll
        for (int off = TPB / 2; off > 0; off >>= 1) {
            if (t < off) r[t] += r[t + off];
            __syncthreads();
        }
        if (t == 0) {
            out[0] = r[0] * (1.0f / (float)(NTOT * NN_SIZE));
            g_done = 0;                     // self-restore for next replay
        }
    }
}

extern "C" void kernel_launch(void* const* d_in, const int* in_sizes, int n_in,
                              void* d_out, int out_size) {
    (void)in_sizes; (void)n_in; (void)out_size;
    const float* pts = (const float*)d_in[0];
    float* out = (float*)d_out;

    k_count  <<<(NTOT + 255) / 256, 256>>>(pts);   // idx 0
    k_scanA  <<<BATCH * NSEG, SCANC_T>>>();        // idx 1
    k_scanB  <<<1, 32>>>();                        // idx 2
    k_scanC  <<<BATCH * NSEG, SCANC_T>>>();        // idx 3  <- ncu -s 5 lands here
    k_scatter<<<(NTOT + 255) / 256, 256>>>(pts);   // idx 4
    k_main   <<<NBLK, TPB>>>(out);                 // idx 5
}